// round 14
// baseline (speedup 1.0000x reference)
#include <cuda_runtime.h>
#include <cuda_fp16.h>
#include <cstdint>

#define BSZ 256
#define MAX_LEN 1024
#define D 256
#define D_ATTN 128

__device__ float g_buf[BSZ * D];   // g[b][j]

// ---------------------------------------------------------------------------
__device__ __forceinline__ uint32_t smem_u32(const void* p) {
    uint32_t a;
    asm("{ .reg .u64 t; cvta.to.shared.u64 t, %1; cvt.u32.u64 %0, t; }"
        : "=r"(a) : "l"(p));
    return a;
}
__device__ __forceinline__ float tanh_ap(float x) {
    float r;
    asm("tanh.approx.f32 %0, %1;" : "=f"(r) : "f"(x));
    return r;
}
__device__ __forceinline__ void mma_f16(float c[4], const uint32_t a[4],
                                        const uint32_t b[2]) {
    asm volatile(
        "mma.sync.aligned.m16n8k16.row.col.f32.f16.f16.f32 "
        "{%0,%1,%2,%3}, {%4,%5,%6,%7}, {%8,%9}, {%0,%1,%2,%3};\n"
        : "+f"(c[0]), "+f"(c[1]), "+f"(c[2]), "+f"(c[3])
        : "r"(a[0]), "r"(a[1]), "r"(a[2]), "r"(a[3]), "r"(b[0]), "r"(b[1]));
}
#define LDSM4(r0, r1, r2, r3, addr)                                           \
    asm volatile("ldmatrix.sync.aligned.m8n8.x4.shared.b16 {%0,%1,%2,%3}, [%4];" \
                 : "=r"(r0), "=r"(r1), "=r"(r2), "=r"(r3) : "r"(addr))

__device__ __forceinline__ uint32_t pack_h2(float x, float y) {
    const __half2 h = __floats2half2_rn(x, y);
    return *(const uint32_t*)&h;
}
__device__ __forceinline__ uint4 pack8(const float4& a, const float4& b) {
    return make_uint4(pack_h2(a.x, a.y), pack_h2(a.z, a.w),
                      pack_h2(b.x, b.y), pack_h2(b.z, b.w));
}

// ---------------------------------------------------------------------------
// k1 body: D[m=a(128), n=b(128)] = w_f[j] . emb_q[b0:b0+128]^T, K=256.
// B: emb_q converted fp32->fp16 once in prologue, resident smem (64KB).
// A: w_f reg-staged + converted, double-buffered 2x16KB. 256 threads.
// ---------------------------------------------------------------------------
#define A_STG 16384
#define B_BASE 32768
#define B_TILE 16384
#define K1_SMEM (B_BASE + 4 * B_TILE + 1024)

__device__ __forceinline__ void k1_body(
    char* dyn,
    const float* __restrict__ emb_q, const float* __restrict__ w_f,
    const float* __restrict__ b_f, const float* __restrict__ w_h,
    const int j, const int b0)
{
    __shared__ float bias_s[D_ATTN], wh_s[D_ATTN];
    __shared__ float red[2][128];

    const int tid  = threadIdx.x;
    const int lane = tid & 31;
    const int wid  = tid >> 5;
    const int wm   = wid >> 2;
    const int wn   = wid & 3;
    const int gid  = lane >> 2;
    const int tid4 = lane & 3;

    const uint32_t raw = smem_u32(dyn);
    const uint32_t dbase = (raw + 1023u) & ~1023u;
    char* dptr = dyn + (dbase - raw);

    if (tid < D_ATTN) {
        bias_s[tid] = b_f[j * D_ATTN + tid];
        wh_s[tid]   = w_h[tid];
    }

    const int c  = tid & 7;
    const int rb = tid >> 3;

    // prologue: B = emb_q[b0:b0+128] fp32 -> fp16 resident smem (once)
#pragma unroll
    for (int kt = 0; kt < 4; kt++) {
#pragma unroll
        for (int i = 0; i < 4; i++) {
            const int r = rb + 32 * i;
            const float* pb = emb_q + (size_t)(b0 + r) * 256 + kt * 64 + c * 8;
            const float4 v0 = *(const float4*)pb;
            const float4 v1 = *(const float4*)(pb + 4);
            *(uint4*)(dptr + B_BASE + kt * B_TILE + r * 128 +
                      ((c ^ (r & 7)) << 4)) = pack8(v0, v1);
        }
    }

    // A tile 0
    const float* Aj = w_f + (size_t)j * D_ATTN * D;
    float4 ra[4][2];
#pragma unroll
    for (int i = 0; i < 4; i++) {
        const int r = rb + 32 * i;
        const float* p = Aj + (size_t)r * 256 + c * 8;
        ra[i][0] = *(const float4*)p;
        ra[i][1] = *(const float4*)(p + 4);
    }
#pragma unroll
    for (int i = 0; i < 4; i++) {
        const int r = rb + 32 * i;
        *(uint4*)(dptr + r * 128 + ((c ^ (r & 7)) << 4)) =
            pack8(ra[i][0], ra[i][1]);
    }
    __syncthreads();

    const int lrow = lane & 7;
    const int half = (lane >> 3) & 1;
    const int hi   = lane >> 4;
    uint32_t roffA[4], swzA[4], roffB[2], swzB[2];
#pragma unroll
    for (int m = 0; m < 4; m++) {
        const int r = wm * 64 + m * 16 + half * 8 + lrow;
        roffA[m] = (uint32_t)r * 128;
        swzA[m]  = (uint32_t)(r & 7);
    }
#pragma unroll
    for (int pf = 0; pf < 2; pf++) {
        const int r = wn * 32 + pf * 16 + half * 8 + lrow;
        roffB[pf] = (uint32_t)r * 128;
        swzB[pf]  = (uint32_t)(r & 7);
    }

    float acc[4][4][4];
#pragma unroll
    for (int m = 0; m < 4; m++)
#pragma unroll
        for (int n = 0; n < 4; n++)
#pragma unroll
            for (int q = 0; q < 4; q++) acc[m][n][q] = 0.0f;

#pragma unroll
    for (int t = 0; t < 4; t++) {
        if (t < 3) {
#pragma unroll
            for (int i = 0; i < 4; i++) {
                const int r = rb + 32 * i;
                const float* p = Aj + (size_t)r * 256 + (t + 1) * 64 + c * 8;
                ra[i][0] = *(const float4*)p;
                ra[i][1] = *(const float4*)(p + 4);
            }
        }

        const uint32_t aB = dbase + (uint32_t)(t & 1) * A_STG;
        const uint32_t bB = dbase + B_BASE + (uint32_t)t * B_TILE;
#pragma unroll
        for (int ks = 0; ks < 4; ks++) {
            const uint32_t ch = (uint32_t)(ks * 2 + hi);
            uint32_t af[4][4], bf[4][2];
#pragma unroll
            for (int m = 0; m < 4; m++)
                LDSM4(af[m][0], af[m][1], af[m][2], af[m][3],
                      aB + roffA[m] + ((ch ^ swzA[m]) << 4));
#pragma unroll
            for (int pf = 0; pf < 2; pf++) {
                uint32_t r0, r1, r2, r3;
                LDSM4(r0, r1, r2, r3, bB + roffB[pf] + ((ch ^ swzB[pf]) << 4));
                bf[2 * pf][0] = r0; bf[2 * pf + 1][0] = r1;
                bf[2 * pf][1] = r2; bf[2 * pf + 1][1] = r3;
            }
#pragma unroll
            for (int m = 0; m < 4; m++)
#pragma unroll
                for (int n = 0; n < 4; n++) mma_f16(acc[m][n], af[m], bf[n]);
        }

        if (t < 3) {
            __syncthreads();
            char* dp = dptr + ((t + 1) & 1) * A_STG;
#pragma unroll
            for (int i = 0; i < 4; i++) {
                const int r = rb + 32 * i;
                *(uint4*)(dp + r * 128 + ((c ^ (r & 7)) << 4)) =
                    pack8(ra[i][0], ra[i][1]);
            }
            __syncthreads();
        }
    }

    // epilogue
    float biasv[4][2], whv[4][2];
#pragma unroll
    for (int m = 0; m < 4; m++)
#pragma unroll
        for (int h = 0; h < 2; h++) {
            const int a = wm * 64 + m * 16 + h * 8 + gid;
            biasv[m][h] = bias_s[a];
            whv[m][h]   = wh_s[a];
        }

#pragma unroll
    for (int n = 0; n < 4; n++) {
        float p0 = 0.0f, p1 = 0.0f;
#pragma unroll
        for (int m = 0; m < 4; m++) {
            p0 += tanh_ap(acc[m][n][0] + biasv[m][0]) * whv[m][0]
                + tanh_ap(acc[m][n][2] + biasv[m][1]) * whv[m][1];
            p1 += tanh_ap(acc[m][n][1] + biasv[m][0]) * whv[m][0]
                + tanh_ap(acc[m][n][3] + biasv[m][1]) * whv[m][1];
        }
#pragma unroll
        for (int o = 4; o <= 16; o <<= 1) {
            p0 += __shfl_xor_sync(0xffffffffu, p0, o);
            p1 += __shfl_xor_sync(0xffffffffu, p1, o);
        }
        if (gid == 0) {
            const int col = wn * 32 + n * 8 + tid4 * 2;
            red[wm][col]     = p0;
            red[wm][col + 1] = p1;
        }
    }
    __syncthreads();
    if (tid < 128)
        g_buf[(size_t)(b0 + tid) * D + j] = red[0][tid] + red[1][tid];
}

// ---------------------------------------------------------------------------
// k2 body: out[b, l0..l0+64) = emb_iseq[b] . g[b]; 8 rows/warp, __ldcs.
// ---------------------------------------------------------------------------
__device__ __forceinline__ void k2_body(
    const float* __restrict__ emb_iseq, float* __restrict__ out,
    const int b, const int l0)
{
    __shared__ float gs[D];
    const int tid = threadIdx.x;
    gs[tid] = g_buf[(size_t)b * D + tid];
    __syncthreads();

    const int warp = tid >> 5;
    const int lane = tid & 31;
    const int l = l0 + warp * 8;

    const float4* base = (const float4*)(emb_iseq + ((size_t)b * MAX_LEN + l) * D);

    float4 e[8][2];
#pragma unroll
    for (int r = 0; r < 8; r++)
#pragma unroll
        for (int i = 0; i < 2; i++)
            e[r][i] = __ldcs(&base[r * 64 + i * 32 + lane]);

    const float4* gv = (const float4*)gs;
    const float4 g0 = gv[lane];
    const float4 g1 = gv[lane + 32];

    float acc[8];
#pragma unroll
    for (int r = 0; r < 8; r++) {
        acc[r] = e[r][0].x * g0.x + e[r][0].y * g0.y + e[r][0].z * g0.z +
                 e[r][0].w * g0.w + e[r][1].x * g1.x + e[r][1].y * g1.y +
                 e[r][1].z * g1.z + e[r][1].w * g1.w;
    }
#pragma unroll
    for (int r = 0; r < 8; r++)
#pragma unroll
        for (int o = 16; o; o >>= 1)
            acc[r] += __shfl_xor_sync(0xffffffffu, acc[r], o);

    if (lane == 0) {
#pragma unroll
        for (int r = 0; r < 8; r++)
            out[(size_t)b * MAX_LEN + l + r] = acc[r];
    }
}

// ---------------------------------------------------------------------------
// Phase 1: k1a (g for b in [0,128)), grid 256.
// ---------------------------------------------------------------------------
__global__ void __launch_bounds__(256, 2) k1_kernel(
    const float* __restrict__ emb_q, const float* __restrict__ w_f,
    const float* __restrict__ b_f, const float* __restrict__ w_h)
{
    extern __shared__ char dyn[];
    k1_body(dyn, emb_q, w_f, b_f, w_h, blockIdx.x, 0);
}

// ---------------------------------------------------------------------------
// Phase 2: mixed kernel, grid 2304.
//   bid % 9 == 0  -> k1 role: g for b in [128,256), j = bid/9   (256 CTAs)
//   else          -> k2 role: out for b in [0,128)              (2048 CTAs)
// Every 9th bid => classic bid->SM round-robin spreads GEMM CTAs evenly.
// ---------------------------------------------------------------------------
__global__ void __launch_bounds__(256, 2) mix_kernel(
    const float* __restrict__ emb_q, const float* __restrict__ emb_iseq,
    const float* __restrict__ w_f, const float* __restrict__ b_f,
    const float* __restrict__ w_h, float* __restrict__ out)
{
    extern __shared__ char dyn[];
    const int bid = blockIdx.x;
    if (bid % 9 == 0) {
        k1_body(dyn, emb_q, w_f, b_f, w_h, bid / 9, 128);
    } else {
        const int k2idx = bid - bid / 9 - 1;    // 0..2047
        const int b  = k2idx >> 4;              // 0..127
        const int l0 = (k2idx & 15) * 64;
        k2_body(emb_iseq, out, b, l0);
    }
}

// ---------------------------------------------------------------------------
// Phase 3: k2b (out for b in [128,256)), grid (16,128).
// ---------------------------------------------------------------------------
__global__ void __launch_bounds__(256) k2_kernel(
    const float* __restrict__ emb_iseq, float* __restrict__ out)
{
    k2_body(emb_iseq, out, 128 + blockIdx.y, blockIdx.x * 64);
}

// ---------------------------------------------------------------------------

extern "C" void kernel_launch(void* const* d_in, const int* in_sizes, int n_in,
                              void* d_out, int out_size)
{
    const float* emb_q    = (const float*)d_in[0];
    const float* emb_iseq = (const float*)d_in[1];
    const float* w_f      = (const float*)d_in[2];
    const float* b_f      = (const float*)d_in[3];
    const float* w_h      = (const float*)d_in[4];
    float* out = (float*)d_out;

    cudaFuncSetAttribute(k1_kernel,
                         cudaFuncAttributeMaxDynamicSharedMemorySize, K1_SMEM);
    cudaFuncSetAttribute(mix_kernel,
                         cudaFuncAttributeMaxDynamicSharedMemorySize, K1_SMEM);

    // phase 1: g for b < 128
    k1_kernel<<<256, 256, K1_SMEM>>>(emb_q, w_f, b_f, w_h);

    // phase 2: g for b >= 128  ||  out for b < 128 (no mutual dependency)
    mix_kernel<<<2304, 256, K1_SMEM>>>(emb_q, emb_iseq, w_f, b_f, w_h, out);

    // phase 3: out for b >= 128
    k2_kernel<<<dim3(16, 128), 256>>>(emb_iseq, out);
}

// round 15
// speedup vs baseline: 1.1890x; 1.1890x over previous
#include <cuda_runtime.h>
#include <cuda_fp16.h>
#include <cstdint>

#define BSZ 256
#define MAX_LEN 1024
#define D 256
#define D_ATTN 128

__device__ float g_buf[BSZ * D];   // g[b][j]

// ---------------------------------------------------------------------------
__device__ __forceinline__ uint32_t smem_u32(const void* p) {
    uint32_t a;
    asm("{ .reg .u64 t; cvta.to.shared.u64 t, %1; cvt.u32.u64 %0, t; }"
        : "=r"(a) : "l"(p));
    return a;
}
__device__ __forceinline__ float tanh_ap(float x) {
    float r;
    asm("tanh.approx.f32 %0, %1;" : "=f"(r) : "f"(x));
    return r;
}
__device__ __forceinline__ void mma_f16(float c[4], const uint32_t a[4],
                                        const uint32_t b[2]) {
    asm volatile(
        "mma.sync.aligned.m16n8k16.row.col.f32.f16.f16.f32 "
        "{%0,%1,%2,%3}, {%4,%5,%6,%7}, {%8,%9}, {%0,%1,%2,%3};\n"
        : "+f"(c[0]), "+f"(c[1]), "+f"(c[2]), "+f"(c[3])
        : "r"(a[0]), "r"(a[1]), "r"(a[2]), "r"(a[3]), "r"(b[0]), "r"(b[1]));
}
#define LDSM4(r0, r1, r2, r3, addr)                                           \
    asm volatile("ldmatrix.sync.aligned.m8n8.x4.shared.b16 {%0,%1,%2,%3}, [%4];" \
                 : "=r"(r0), "=r"(r1), "=r"(r2), "=r"(r3) : "r"(addr))

__device__ __forceinline__ uint32_t pack_h2(float x, float y) {
    const __half2 h = __floats2half2_rn(x, y);
    return *(const uint32_t*)&h;
}
__device__ __forceinline__ uint4 pack8(const float4& a, const float4& b) {
    return make_uint4(pack_h2(a.x, a.y), pack_h2(a.z, a.w),
                      pack_h2(b.x, b.y), pack_h2(b.z, b.w));
}

// ---------------------------------------------------------------------------
// Kernel 1: one CTA per j. D[m=a(128), n=b(256)] = w_f[j] . emb_q^T, K=256,
// fp16 mma m16n8k16, fp32 accum. B (emb_q, 128KB as fp16) made CTA-resident
// in the prologue by reading fp32 emb_q from L2 and converting inline
// (replaces the old pre-convert kernel). A (w_f) converted inline,
// 2-stage 16KB double buffer. 8 warps: wm = wid>>2, wn = wid&3.
// smem rows = 128B (64 fp16), swizzle chunk c' = c ^ (r&7).
// ---------------------------------------------------------------------------
#define A_STG 16384
#define B_BASE 32768
#define B_TILE 32768
#define K1_SMEM (B_BASE + 4 * B_TILE + 1024)   // ~161KB

__global__ void __launch_bounds__(256, 1) k1_mma(
    const float* __restrict__ emb_q,   // [BSZ, D]
    const float* __restrict__ w_f,     // [D, D_ATTN, D]
    const float* __restrict__ b_f,     // [D, D_ATTN]
    const float* __restrict__ w_h)     // [D_ATTN]
{
    extern __shared__ char dyn[];
    __shared__ float bias_s[D_ATTN], wh_s[D_ATTN];
    __shared__ float red[2][256];

    const int j    = blockIdx.x;
    const int tid  = threadIdx.x;
    const int lane = tid & 31;
    const int wid  = tid >> 5;
    const int wm   = wid >> 2;
    const int wn   = wid & 3;
    const int gid  = lane >> 2;
    const int tid4 = lane & 3;

    const uint32_t raw = smem_u32(dyn);
    const uint32_t dbase = (raw + 1023u) & ~1023u;
    char* dptr = dyn + (dbase - raw);

    if (tid < D_ATTN) {
        bias_s[tid] = b_f[j * D_ATTN + tid];
        wh_s[tid]   = w_h[tid];
    }

    const int c  = tid & 7;       // 16B chunk within 128B row
    const int rb = tid >> 3;      // row base (0..31)

    // ---- prologue: B = full emb_q fp32 -> fp16 resident smem (once per CTA)
#pragma unroll
    for (int kt = 0; kt < 4; kt++) {
        float4 v[8][2];
#pragma unroll
        for (int i = 0; i < 8; i++) {
            const int r = rb + 32 * i;  // 0..255
            const float* pb = emb_q + (size_t)r * 256 + kt * 64 + c * 8;
            v[i][0] = *(const float4*)pb;
            v[i][1] = *(const float4*)(pb + 4);
        }
#pragma unroll
        for (int i = 0; i < 8; i++) {
            const int r = rb + 32 * i;
            *(uint4*)(dptr + B_BASE + kt * B_TILE + r * 128 +
                      ((c ^ (r & 7)) << 4)) = pack8(v[i][0], v[i][1]);
        }
    }

    // ---- A tile 0: load + convert + STS
    const float* Aj = w_f + (size_t)j * D_ATTN * D;
    float4 ra[4][2];
#pragma unroll
    for (int i = 0; i < 4; i++) {
        const int r = rb + 32 * i;  // 0..127
        const float* p = Aj + (size_t)r * 256 + c * 8;
        ra[i][0] = *(const float4*)p;
        ra[i][1] = *(const float4*)(p + 4);
    }
#pragma unroll
    for (int i = 0; i < 4; i++) {
        const int r = rb + 32 * i;
        *(uint4*)(dptr + r * 128 + ((c ^ (r & 7)) << 4)) =
            pack8(ra[i][0], ra[i][1]);
    }
    __syncthreads();

    // ---- ldmatrix per-thread bases
    const int lrow = lane & 7;
    const int half = (lane >> 3) & 1;
    const int hi   = lane >> 4;
    uint32_t roffA[4], swzA[4], roffB[4], swzB[4];
#pragma unroll
    for (int m = 0; m < 4; m++) {
        const int r = wm * 64 + m * 16 + half * 8 + lrow;
        roffA[m] = (uint32_t)r * 128;
        swzA[m]  = (uint32_t)(r & 7);
    }
#pragma unroll
    for (int p = 0; p < 4; p++) {
        const int r = wn * 64 + p * 16 + half * 8 + lrow;
        roffB[p] = (uint32_t)r * 128;
        swzB[p]  = (uint32_t)(r & 7);
    }

    float acc[4][8][4];
#pragma unroll
    for (int m = 0; m < 4; m++)
#pragma unroll
        for (int n = 0; n < 8; n++)
#pragma unroll
            for (int q = 0; q < 4; q++) acc[m][n][q] = 0.0f;

    // ---- main loop: 4 k-tiles of 64 (A double-buffered, B resident)
#pragma unroll
    for (int t = 0; t < 4; t++) {
        // prefetch next A tile into regs
        if (t < 3) {
#pragma unroll
            for (int i = 0; i < 4; i++) {
                const int r = rb + 32 * i;
                const float* p = Aj + (size_t)r * 256 + (t + 1) * 64 + c * 8;
                ra[i][0] = *(const float4*)p;
                ra[i][1] = *(const float4*)(p + 4);
            }
        }

        // compute tile t
        const uint32_t aB = dbase + (uint32_t)(t & 1) * A_STG;
        const uint32_t bB = dbase + B_BASE + (uint32_t)t * B_TILE;
#pragma unroll
        for (int ks = 0; ks < 4; ks++) {
            const uint32_t ch = (uint32_t)(ks * 2 + hi);
            uint32_t af[4][4], bf[8][2];
#pragma unroll
            for (int m = 0; m < 4; m++)
                LDSM4(af[m][0], af[m][1], af[m][2], af[m][3],
                      aB + roffA[m] + ((ch ^ swzA[m]) << 4));
#pragma unroll
            for (int p = 0; p < 4; p++) {
                uint32_t r0, r1, r2, r3;
                LDSM4(r0, r1, r2, r3, bB + roffB[p] + ((ch ^ swzB[p]) << 4));
                bf[2 * p][0] = r0; bf[2 * p + 1][0] = r1;
                bf[2 * p][1] = r2; bf[2 * p + 1][1] = r3;
            }
#pragma unroll
            for (int m = 0; m < 4; m++)
#pragma unroll
                for (int n = 0; n < 8; n++) mma_f16(acc[m][n], af[m], bf[n]);
        }

        if (t < 3) {
            __syncthreads();
            char* dp = dptr + ((t + 1) & 1) * A_STG;
#pragma unroll
            for (int i = 0; i < 4; i++) {
                const int r = rb + 32 * i;
                *(uint4*)(dp + r * 128 + ((c ^ (r & 7)) << 4)) =
                    pack8(ra[i][0], ra[i][1]);
            }
            __syncthreads();
        }
    }

    // ---- epilogue: g[b][j] = sum_a tanh(D[a,b] + bias[a]) * wh[a]
    float biasv[4][2], whv[4][2];
#pragma unroll
    for (int m = 0; m < 4; m++)
#pragma unroll
        for (int h = 0; h < 2; h++) {
            const int a = wm * 64 + m * 16 + h * 8 + gid;
            biasv[m][h] = bias_s[a];
            whv[m][h]   = wh_s[a];
        }

#pragma unroll
    for (int n = 0; n < 8; n++) {
        float p0 = 0.0f, p1 = 0.0f;
#pragma unroll
        for (int m = 0; m < 4; m++) {
            p0 += tanh_ap(acc[m][n][0] + biasv[m][0]) * whv[m][0]
                + tanh_ap(acc[m][n][2] + biasv[m][1]) * whv[m][1];
            p1 += tanh_ap(acc[m][n][1] + biasv[m][0]) * whv[m][0]
                + tanh_ap(acc[m][n][3] + biasv[m][1]) * whv[m][1];
        }
#pragma unroll
        for (int o = 4; o <= 16; o <<= 1) {
            p0 += __shfl_xor_sync(0xffffffffu, p0, o);
            p1 += __shfl_xor_sync(0xffffffffu, p1, o);
        }
        if (gid == 0) {
            const int col = wn * 64 + n * 8 + tid4 * 2;
            red[wm][col]     = p0;
            red[wm][col + 1] = p1;
        }
    }
    __syncthreads();
    g_buf[(size_t)tid * D + j] = red[0][tid] + red[1][tid];
}

// ---------------------------------------------------------------------------
// Kernel 2: out[b,l] = sum_j emb_iseq[b,l,j] * g[b,j]
// Champion config (measured 80.2% DRAM): 8 rows/warp, __ldcs, grid (16,256).
// ---------------------------------------------------------------------------
__global__ void __launch_bounds__(256) k2_weight(
    const float* __restrict__ emb_iseq,  // [BSZ, MAX_LEN, D]
    float* __restrict__ out)             // [BSZ, MAX_LEN]
{
    const int b   = blockIdx.y;
    const int l0  = blockIdx.x * 64;
    const int tid = threadIdx.x;

    __shared__ float gs[D];
    gs[tid] = g_buf[(size_t)b * D + tid];
    __syncthreads();

    const int warp = tid >> 5;
    const int lane = tid & 31;
    const int l = l0 + warp * 8;

    const float4* base = (const float4*)(emb_iseq + ((size_t)b * MAX_LEN + l) * D);

    float4 e[8][2];
#pragma unroll
    for (int r = 0; r < 8; r++)
#pragma unroll
        for (int i = 0; i < 2; i++)
            e[r][i] = __ldcs(&base[r * 64 + i * 32 + lane]);

    const float4* gv = (const float4*)gs;
    const float4 g0 = gv[lane];
    const float4 g1 = gv[lane + 32];

    float acc[8];
#pragma unroll
    for (int r = 0; r < 8; r++) {
        acc[r] = e[r][0].x * g0.x + e[r][0].y * g0.y + e[r][0].z * g0.z +
                 e[r][0].w * g0.w + e[r][1].x * g1.x + e[r][1].y * g1.y +
                 e[r][1].z * g1.z + e[r][1].w * g1.w;
    }
#pragma unroll
    for (int r = 0; r < 8; r++)
#pragma unroll
        for (int o = 16; o; o >>= 1)
            acc[r] += __shfl_xor_sync(0xffffffffu, acc[r], o);

    if (lane == 0) {
#pragma unroll
        for (int r = 0; r < 8; r++)
            out[(size_t)b * MAX_LEN + l + r] = acc[r];
    }
}

// ---------------------------------------------------------------------------

extern "C" void kernel_launch(void* const* d_in, const int* in_sizes, int n_in,
                              void* d_out, int out_size)
{
    const float* emb_q    = (const float*)d_in[0];
    const float* emb_iseq = (const float*)d_in[1];
    const float* w_f      = (const float*)d_in[2];
    const float* b_f      = (const float*)d_in[3];
    const float* w_h      = (const float*)d_in[4];
    float* out = (float*)d_out;

    cudaFuncSetAttribute(k1_mma, cudaFuncAttributeMaxDynamicSharedMemorySize,
                         K1_SMEM);

    k1_mma<<<D, 256, K1_SMEM>>>(emb_q, w_f, b_f, w_h);

    dim3 g2(MAX_LEN / 64, BSZ);
    k2_weight<<<g2, 256>>>(emb_iseq, out);
}

// round 16
// speedup vs baseline: 1.2896x; 1.0847x over previous
#include <cuda_runtime.h>
#include <cuda_fp16.h>
#include <cstdint>

#define BSZ 256
#define MAX_LEN 1024
#define D 256
#define D_ATTN 128

__device__ float g_buf[BSZ * D];   // g[b][j]

// ---------------------------------------------------------------------------
__device__ __forceinline__ uint32_t smem_u32(const void* p) {
    uint32_t a;
    asm("{ .reg .u64 t; cvta.to.shared.u64 t, %1; cvt.u32.u64 %0, t; }"
        : "=r"(a) : "l"(p));
    return a;
}
__device__ __forceinline__ float tanh_ap(float x) {
    float r;
    asm("tanh.approx.f32 %0, %1;" : "=f"(r) : "f"(x));
    return r;
}
__device__ __forceinline__ void mma_f16(float c[4], const uint32_t a[4],
                                        const uint32_t b[2]) {
    asm volatile(
        "mma.sync.aligned.m16n8k16.row.col.f32.f16.f16.f32 "
        "{%0,%1,%2,%3}, {%4,%5,%6,%7}, {%8,%9}, {%0,%1,%2,%3};\n"
        : "+f"(c[0]), "+f"(c[1]), "+f"(c[2]), "+f"(c[3])
        : "r"(a[0]), "r"(a[1]), "r"(a[2]), "r"(a[3]), "r"(b[0]), "r"(b[1]));
}
#define LDSM4(r0, r1, r2, r3, addr)                                           \
    asm volatile("ldmatrix.sync.aligned.m8n8.x4.shared.b16 {%0,%1,%2,%3}, [%4];" \
                 : "=r"(r0), "=r"(r1), "=r"(r2), "=r"(r3) : "r"(addr))

__device__ __forceinline__ uint32_t pack_h2(float x, float y) {
    const __half2 h = __floats2half2_rn(x, y);
    return *(const uint32_t*)&h;
}
__device__ __forceinline__ uint4 pack8(const float4& a, const float4& b) {
    return make_uint4(pack_h2(a.x, a.y), pack_h2(a.z, a.w),
                      pack_h2(b.x, b.y), pack_h2(b.z, b.w));
}

// ---------------------------------------------------------------------------
// Kernel 1: one CTA per j. D[m=a(128), n=b(256)] = w_f[j] . emb_q^T, K=256.
// B (emb_q fp16) built lazily: tile 0 in prologue, tiles t+1 converted in
// the inter-tile sync window (hidden under warp stagger + HMMA).
// A (w_f) reg-staged + converted, 2-stage double buffer.
// Fires griddepcontrol.launch_dependents at entry (PDL overlap with k2).
// ---------------------------------------------------------------------------
#define A_STG 16384
#define B_BASE 32768
#define B_TILE 32768
#define K1_SMEM (B_BASE + 4 * B_TILE + 1024)   // ~161KB

__global__ void __launch_bounds__(256, 1) k1_mma(
    const float* __restrict__ emb_q,   // [BSZ, D]
    const float* __restrict__ w_f,     // [D, D_ATTN, D]
    const float* __restrict__ b_f,     // [D, D_ATTN]
    const float* __restrict__ w_h)     // [D_ATTN]
{
    extern __shared__ char dyn[];
    __shared__ float bias_s[D_ATTN], wh_s[D_ATTN];
    __shared__ float red[2][256];

    // allow the dependent k2 grid to start streaming emb_iseq immediately
    asm volatile("griddepcontrol.launch_dependents;");

    const int j    = blockIdx.x;
    const int tid  = threadIdx.x;
    const int lane = tid & 31;
    const int wid  = tid >> 5;
    const int wm   = wid >> 2;
    const int wn   = wid & 3;
    const int gid  = lane >> 2;
    const int tid4 = lane & 3;

    const uint32_t raw = smem_u32(dyn);
    const uint32_t dbase = (raw + 1023u) & ~1023u;
    char* dptr = dyn + (dbase - raw);

    if (tid < D_ATTN) {
        bias_s[tid] = b_f[j * D_ATTN + tid];
        wh_s[tid]   = w_h[tid];
    }

    const int c  = tid & 7;       // 16B chunk within 128B row
    const int rb = tid >> 3;      // row base (0..31)

    // ---- prologue: B k-tile 0 only (emb_q fp32 -> fp16, 16MB chip burst)
    {
        float4 v[8][2];
#pragma unroll
        for (int i = 0; i < 8; i++) {
            const int r = rb + 32 * i;  // 0..255
            const float* pb = emb_q + (size_t)r * 256 + c * 8;
            v[i][0] = *(const float4*)pb;
            v[i][1] = *(const float4*)(pb + 4);
        }
#pragma unroll
        for (int i = 0; i < 8; i++) {
            const int r = rb + 32 * i;
            *(uint4*)(dptr + B_BASE + r * 128 + ((c ^ (r & 7)) << 4)) =
                pack8(v[i][0], v[i][1]);
        }
    }

    // ---- A tile 0: load + convert + STS
    const float* Aj = w_f + (size_t)j * D_ATTN * D;
    float4 ra[4][2];
#pragma unroll
    for (int i = 0; i < 4; i++) {
        const int r = rb + 32 * i;  // 0..127
        const float* p = Aj + (size_t)r * 256 + c * 8;
        ra[i][0] = *(const float4*)p;
        ra[i][1] = *(const float4*)(p + 4);
    }
#pragma unroll
    for (int i = 0; i < 4; i++) {
        const int r = rb + 32 * i;
        *(uint4*)(dptr + r * 128 + ((c ^ (r & 7)) << 4)) =
            pack8(ra[i][0], ra[i][1]);
    }
    __syncthreads();

    // ---- ldmatrix per-thread bases
    const int lrow = lane & 7;
    const int half = (lane >> 3) & 1;
    const int hi   = lane >> 4;
    uint32_t roffA[4], swzA[4], roffB[4], swzB[4];
#pragma unroll
    for (int m = 0; m < 4; m++) {
        const int r = wm * 64 + m * 16 + half * 8 + lrow;
        roffA[m] = (uint32_t)r * 128;
        swzA[m]  = (uint32_t)(r & 7);
    }
#pragma unroll
    for (int p = 0; p < 4; p++) {
        const int r = wn * 64 + p * 16 + half * 8 + lrow;
        roffB[p] = (uint32_t)r * 128;
        swzB[p]  = (uint32_t)(r & 7);
    }

    float acc[4][8][4];
#pragma unroll
    for (int m = 0; m < 4; m++)
#pragma unroll
        for (int n = 0; n < 8; n++)
#pragma unroll
            for (int q = 0; q < 4; q++) acc[m][n][q] = 0.0f;

    // ---- main loop: 4 k-tiles of 64
#pragma unroll
    for (int t = 0; t < 4; t++) {
        // prefetch next A tile into regs
        if (t < 3) {
#pragma unroll
            for (int i = 0; i < 4; i++) {
                const int r = rb + 32 * i;
                const float* p = Aj + (size_t)r * 256 + (t + 1) * 64 + c * 8;
                ra[i][0] = *(const float4*)p;
                ra[i][1] = *(const float4*)(p + 4);
            }
        }

        // compute tile t
        const uint32_t aB = dbase + (uint32_t)(t & 1) * A_STG;
        const uint32_t bB = dbase + B_BASE + (uint32_t)t * B_TILE;
#pragma unroll
        for (int ks = 0; ks < 4; ks++) {
            const uint32_t ch = (uint32_t)(ks * 2 + hi);
            uint32_t af[4][4], bf[8][2];
#pragma unroll
            for (int m = 0; m < 4; m++)
                LDSM4(af[m][0], af[m][1], af[m][2], af[m][3],
                      aB + roffA[m] + ((ch ^ swzA[m]) << 4));
#pragma unroll
            for (int p = 0; p < 4; p++) {
                uint32_t r0, r1, r2, r3;
                LDSM4(r0, r1, r2, r3, bB + roffB[p] + ((ch ^ swzB[p]) << 4));
                bf[2 * p][0] = r0; bf[2 * p + 1][0] = r1;
                bf[2 * p][1] = r2; bf[2 * p + 1][1] = r3;
            }
#pragma unroll
            for (int m = 0; m < 4; m++)
#pragma unroll
                for (int n = 0; n < 8; n++) mma_f16(acc[m][n], af[m], bf[n]);
        }

        if (t < 3) {
            // B tile t+1 chunk 0 loads (issue before the barrier to hide lat)
            float4 w0[4][2];
#pragma unroll
            for (int i = 0; i < 4; i++) {
                const int r = rb + 32 * i;                 // 0..127
                const float* pb =
                    emb_q + (size_t)r * 256 + (t + 1) * 64 + c * 8;
                w0[i][0] = *(const float4*)pb;
                w0[i][1] = *(const float4*)(pb + 4);
            }
            __syncthreads();

            char* dp = dptr + ((t + 1) & 1) * A_STG;
            char* bp = dptr + B_BASE + (t + 1) * B_TILE;
#pragma unroll
            for (int i = 0; i < 4; i++) {
                const int r = rb + 32 * i;
                *(uint4*)(dp + r * 128 + ((c ^ (r & 7)) << 4)) =
                    pack8(ra[i][0], ra[i][1]);
                *(uint4*)(bp + r * 128 + ((c ^ (r & 7)) << 4)) =
                    pack8(w0[i][0], w0[i][1]);
            }
            // B tile t+1 chunk 1 (rows 128..255)
#pragma unroll
            for (int i = 0; i < 4; i++) {
                const int r = rb + 128 + 32 * i;
                const float* pb =
                    emb_q + (size_t)r * 256 + (t + 1) * 64 + c * 8;
                const float4 u0 = *(const float4*)pb;
                const float4 u1 = *(const float4*)(pb + 4);
                *(uint4*)(bp + r * 128 + ((c ^ (r & 7)) << 4)) = pack8(u0, u1);
            }
            __syncthreads();
        }
    }

    // ---- epilogue: g[b][j] = sum_a tanh(D[a,b] + bias[a]) * wh[a]
    float biasv[4][2], whv[4][2];
#pragma unroll
    for (int m = 0; m < 4; m++)
#pragma unroll
        for (int h = 0; h < 2; h++) {
            const int a = wm * 64 + m * 16 + h * 8 + gid;
            biasv[m][h] = bias_s[a];
            whv[m][h]   = wh_s[a];
        }

#pragma unroll
    for (int n = 0; n < 8; n++) {
        float p0 = 0.0f, p1 = 0.0f;
#pragma unroll
        for (int m = 0; m < 4; m++) {
            p0 += tanh_ap(acc[m][n][0] + biasv[m][0]) * whv[m][0]
                + tanh_ap(acc[m][n][2] + biasv[m][1]) * whv[m][1];
            p1 += tanh_ap(acc[m][n][1] + biasv[m][0]) * whv[m][0]
                + tanh_ap(acc[m][n][3] + biasv[m][1]) * whv[m][1];
        }
#pragma unroll
        for (int o = 4; o <= 16; o <<= 1) {
            p0 += __shfl_xor_sync(0xffffffffu, p0, o);
            p1 += __shfl_xor_sync(0xffffffffu, p1, o);
        }
        if (gid == 0) {
            const int col = wn * 64 + n * 8 + tid4 * 2;
            red[wm][col]     = p0;
            red[wm][col + 1] = p1;
        }
    }
    __syncthreads();
    g_buf[(size_t)tid * D + j] = red[0][tid] + red[1][tid];
}

// ---------------------------------------------------------------------------
// Kernel 2: out[b,l] = sum_j emb_iseq[b,l,j] * g[b,j]
// PDL: issue all emb_iseq loads (g-independent) BEFORE griddepcontrol.wait,
// then load g and compute. Under plain launch both griddep ops are no-ops.
// ---------------------------------------------------------------------------
__global__ void __launch_bounds__(256) k2_weight(
    const float* __restrict__ emb_iseq,  // [BSZ, MAX_LEN, D]
    float* __restrict__ out)             // [BSZ, MAX_LEN]
{
    const int b   = blockIdx.y;
    const int l0  = blockIdx.x * 64;
    const int tid = threadIdx.x;
    const int warp = tid >> 5;
    const int lane = tid & 31;
    const int l = l0 + warp * 8;

    const float4* base = (const float4*)(emb_iseq + ((size_t)b * MAX_LEN + l) * D);

    float4 e[8][2];
#pragma unroll
    for (int r = 0; r < 8; r++)
#pragma unroll
        for (int i = 0; i < 2; i++)
            e[r][i] = __ldcs(&base[r * 64 + i * 32 + lane]);

    // wait for k1 grid completion (g_buf ready)
    asm volatile("griddepcontrol.wait;" ::: "memory");

    __shared__ float gs[D];
    gs[tid] = g_buf[(size_t)b * D + tid];
    __syncthreads();

    const float4* gv = (const float4*)gs;
    const float4 g0 = gv[lane];
    const float4 g1 = gv[lane + 32];

    float acc[8];
#pragma unroll
    for (int r = 0; r < 8; r++) {
        acc[r] = e[r][0].x * g0.x + e[r][0].y * g0.y + e[r][0].z * g0.z +
                 e[r][0].w * g0.w + e[r][1].x * g1.x + e[r][1].y * g1.y +
                 e[r][1].z * g1.z + e[r][1].w * g1.w;
    }
#pragma unroll
    for (int r = 0; r < 8; r++)
#pragma unroll
        for (int o = 16; o; o >>= 1)
            acc[r] += __shfl_xor_sync(0xffffffffu, acc[r], o);

    if (lane == 0) {
#pragma unroll
        for (int r = 0; r < 8; r++)
            out[(size_t)b * MAX_LEN + l + r] = acc[r];
    }
}

// ---------------------------------------------------------------------------

extern "C" void kernel_launch(void* const* d_in, const int* in_sizes, int n_in,
                              void* d_out, int out_size)
{
    const float* emb_q    = (const float*)d_in[0];
    const float* emb_iseq = (const float*)d_in[1];
    const float* w_f      = (const float*)d_in[2];
    const float* b_f      = (const float*)d_in[3];
    const float* w_h      = (const float*)d_in[4];
    float* out = (float*)d_out;

    static int pdl_ok = -1;
    if (pdl_ok < 0) {
        cudaFuncSetAttribute(k1_mma,
                             cudaFuncAttributeMaxDynamicSharedMemorySize,
                             K1_SMEM);
        pdl_ok = 1;   // decided on first (uncaptured) call below
    }

    k1_mma<<<D, 256, K1_SMEM>>>(emb_q, w_f, b_f, w_h);

    const dim3 g2(MAX_LEN / 64, BSZ);
    if (pdl_ok == 1) {
        cudaLaunchAttribute attr[1];
        attr[0].id = cudaLaunchAttributeProgrammaticStreamSerialization;
        attr[0].val.programmaticStreamSerializationAllowed = 1;
        cudaLaunchConfig_t cfg = {};
        cfg.gridDim = g2;
        cfg.blockDim = dim3(256, 1, 1);
        cfg.dynamicSmemBytes = 0;
        cfg.stream = 0;
        cfg.attrs = attr;
        cfg.numAttrs = 1;
        if (cudaLaunchKernelEx(&cfg, k2_weight, emb_iseq, out) != cudaSuccess) {
            pdl_ok = 0;
            cudaGetLastError();   // clear; fall through to plain launch
            k2_weight<<<g2, 256>>>(emb_iseq, out);
        }
    } else {
        k2_weight<<<g2, 256>>>(emb_iseq, out);
    }
}

// round 17
// speedup vs baseline: 1.3287x; 1.0303x over previous
#include <cuda_runtime.h>
#include <cuda_fp16.h>
#include <cstdint>

#define BSZ 256
#define MAX_LEN 1024
#define D 256
#define D_ATTN 128
#define NCTA1 148

__device__ float g_buf[BSZ * D];   // g[b][j]

// ---------------------------------------------------------------------------
__device__ __forceinline__ uint32_t smem_u32(const void* p) {
    uint32_t a;
    asm("{ .reg .u64 t; cvta.to.shared.u64 t, %1; cvt.u32.u64 %0, t; }"
        : "=r"(a) : "l"(p));
    return a;
}
__device__ __forceinline__ float tanh_ap(float x) {
    float r;
    asm("tanh.approx.f32 %0, %1;" : "=f"(r) : "f"(x));
    return r;
}
__device__ __forceinline__ void mma_f16(float c[4], const uint32_t a[4],
                                        const uint32_t b[2]) {
    asm volatile(
        "mma.sync.aligned.m16n8k16.row.col.f32.f16.f16.f32 "
        "{%0,%1,%2,%3}, {%4,%5,%6,%7}, {%8,%9}, {%0,%1,%2,%3};\n"
        : "+f"(c[0]), "+f"(c[1]), "+f"(c[2]), "+f"(c[3])
        : "r"(a[0]), "r"(a[1]), "r"(a[2]), "r"(a[3]), "r"(b[0]), "r"(b[1]));
}
#define LDSM4(r0, r1, r2, r3, addr)                                           \
    asm volatile("ldmatrix.sync.aligned.m8n8.x4.shared.b16 {%0,%1,%2,%3}, [%4];" \
                 : "=r"(r0), "=r"(r1), "=r"(r2), "=r"(r3) : "r"(addr))

__device__ __forceinline__ uint32_t pack_h2(float x, float y) {
    const __half2 h = __floats2half2_rn(x, y);
    return *(const uint32_t*)&h;
}
__device__ __forceinline__ uint4 pack8(const float4& a, const float4& b) {
    return make_uint4(pack_h2(a.x, a.y), pack_h2(a.z, a.w),
                      pack_h2(b.x, b.y), pack_h2(b.z, b.w));
}

// ---------------------------------------------------------------------------
// Kernel 1: 148 CTAs; CTA handles j in {cta, cta+148} (108x2 + 40x1).
// D[m=a(128), n=b(256)] = w_f[j] . emb_q^T, K=256, fp16 mma, fp32 accum.
// B (emb_q fp16, 128KB, j-INDEPENDENT): built lazily during task 0 (tile 0
// in prologue, tiles 1-3 in the inter-tile sync windows), REUSED by task 1.
// A (w_f) reg-staged + converted, 2-stage double buffer per task.
// griddepcontrol.launch_dependents at entry (PDL overlap with k2).
// ---------------------------------------------------------------------------
#define A_STG 16384
#define B_BASE 32768
#define B_TILE 32768
#define K1_SMEM (B_BASE + 4 * B_TILE + 1024)   // ~161KB

__global__ void __launch_bounds__(256, 1) k1_mma(
    const float* __restrict__ emb_q,   // [BSZ, D]
    const float* __restrict__ w_f,     // [D, D_ATTN, D]
    const float* __restrict__ b_f,     // [D, D_ATTN]
    const float* __restrict__ w_h)     // [D_ATTN]
{
    extern __shared__ char dyn[];
    __shared__ float bias_s[D_ATTN], wh_s[D_ATTN];
    __shared__ float red[2][256];

    asm volatile("griddepcontrol.launch_dependents;");

    const int cta  = blockIdx.x;
    const int tid  = threadIdx.x;
    const int lane = tid & 31;
    const int wid  = tid >> 5;
    const int wm   = wid >> 2;
    const int wn   = wid & 3;
    const int gid  = lane >> 2;
    const int tid4 = lane & 3;

    const uint32_t raw = smem_u32(dyn);
    const uint32_t dbase = (raw + 1023u) & ~1023u;
    char* dptr = dyn + (dbase - raw);

    if (tid < D_ATTN) wh_s[tid] = w_h[tid];

    const int c  = tid & 7;       // 16B chunk within 128B row
    const int rb = tid >> 3;      // row base (0..31)

    // ---- ldmatrix per-thread bases (task-invariant)
    const int lrow = lane & 7;
    const int half = (lane >> 3) & 1;
    const int hi   = lane >> 4;
    uint32_t roffA[4], swzA[4], roffB[4], swzB[4];
#pragma unroll
    for (int m = 0; m < 4; m++) {
        const int r = wm * 64 + m * 16 + half * 8 + lrow;
        roffA[m] = (uint32_t)r * 128;
        swzA[m]  = (uint32_t)(r & 7);
    }
#pragma unroll
    for (int p = 0; p < 4; p++) {
        const int r = wn * 64 + p * 16 + half * 8 + lrow;
        roffB[p] = (uint32_t)r * 128;
        swzB[p]  = (uint32_t)(r & 7);
    }

    const int ntask = (cta < D - NCTA1) ? 2 : 1;

    for (int task = 0; task < ntask; task++) {
        const int j = cta + task * NCTA1;
        const float* Aj = w_f + (size_t)j * D_ATTN * D;

        if (task == 0) {
            // ---- prologue: B k-tile 0 (emb_q fp32 -> fp16)
            float4 v[8][2];
#pragma unroll
            for (int i = 0; i < 8; i++) {
                const int r = rb + 32 * i;  // 0..255
                const float* pb = emb_q + (size_t)r * 256 + c * 8;
                v[i][0] = *(const float4*)pb;
                v[i][1] = *(const float4*)(pb + 4);
            }
#pragma unroll
            for (int i = 0; i < 8; i++) {
                const int r = rb + 32 * i;
                *(uint4*)(dptr + B_BASE + r * 128 + ((c ^ (r & 7)) << 4)) =
                    pack8(v[i][0], v[i][1]);
            }
        }

        // ---- A tile 0: load + convert + STS
        float4 ra[4][2];
#pragma unroll
        for (int i = 0; i < 4; i++) {
            const int r = rb + 32 * i;  // 0..127
            const float* p = Aj + (size_t)r * 256 + c * 8;
            ra[i][0] = *(const float4*)p;
            ra[i][1] = *(const float4*)(p + 4);
        }
#pragma unroll
        for (int i = 0; i < 4; i++) {
            const int r = rb + 32 * i;
            *(uint4*)(dptr + r * 128 + ((c ^ (r & 7)) << 4)) =
                pack8(ra[i][0], ra[i][1]);
        }
        if (tid < D_ATTN) bias_s[tid] = b_f[j * D_ATTN + tid];
        __syncthreads();

        float acc[4][8][4];
#pragma unroll
        for (int m = 0; m < 4; m++)
#pragma unroll
            for (int n = 0; n < 8; n++)
#pragma unroll
                for (int q = 0; q < 4; q++) acc[m][n][q] = 0.0f;

        // ---- main loop: 4 k-tiles of 64
#pragma unroll
        for (int t = 0; t < 4; t++) {
            if (t < 3) {
#pragma unroll
                for (int i = 0; i < 4; i++) {
                    const int r = rb + 32 * i;
                    const float* p = Aj + (size_t)r * 256 + (t + 1) * 64 + c * 8;
                    ra[i][0] = *(const float4*)p;
                    ra[i][1] = *(const float4*)(p + 4);
                }
            }

            const uint32_t aB = dbase + (uint32_t)(t & 1) * A_STG;
            const uint32_t bB = dbase + B_BASE + (uint32_t)t * B_TILE;
#pragma unroll
            for (int ks = 0; ks < 4; ks++) {
                const uint32_t ch = (uint32_t)(ks * 2 + hi);
                uint32_t af[4][4], bf[8][2];
#pragma unroll
                for (int m = 0; m < 4; m++)
                    LDSM4(af[m][0], af[m][1], af[m][2], af[m][3],
                          aB + roffA[m] + ((ch ^ swzA[m]) << 4));
#pragma unroll
                for (int p = 0; p < 4; p++) {
                    uint32_t r0, r1, r2, r3;
                    LDSM4(r0, r1, r2, r3, bB + roffB[p] + ((ch ^ swzB[p]) << 4));
                    bf[2 * p][0] = r0; bf[2 * p + 1][0] = r1;
                    bf[2 * p][1] = r2; bf[2 * p + 1][1] = r3;
                }
#pragma unroll
                for (int m = 0; m < 4; m++)
#pragma unroll
                    for (int n = 0; n < 8; n++) mma_f16(acc[m][n], af[m], bf[n]);
            }

            if (t < 3) {
                if (task == 0) {
                    // B tile t+1 chunk 0 loads (issued pre-barrier)
                    float4 w0[4][2];
#pragma unroll
                    for (int i = 0; i < 4; i++) {
                        const int r = rb + 32 * i;  // 0..127
                        const float* pb =
                            emb_q + (size_t)r * 256 + (t + 1) * 64 + c * 8;
                        w0[i][0] = *(const float4*)pb;
                        w0[i][1] = *(const float4*)(pb + 4);
                    }
                    __syncthreads();
                    char* dp = dptr + ((t + 1) & 1) * A_STG;
                    char* bp = dptr + B_BASE + (t + 1) * B_TILE;
#pragma unroll
                    for (int i = 0; i < 4; i++) {
                        const int r = rb + 32 * i;
                        *(uint4*)(dp + r * 128 + ((c ^ (r & 7)) << 4)) =
                            pack8(ra[i][0], ra[i][1]);
                        *(uint4*)(bp + r * 128 + ((c ^ (r & 7)) << 4)) =
                            pack8(w0[i][0], w0[i][1]);
                    }
                    // B tile t+1 chunk 1 (rows 128..255)
#pragma unroll
                    for (int i = 0; i < 4; i++) {
                        const int r = rb + 128 + 32 * i;
                        const float* pb =
                            emb_q + (size_t)r * 256 + (t + 1) * 64 + c * 8;
                        const float4 u0 = *(const float4*)pb;
                        const float4 u1 = *(const float4*)(pb + 4);
                        *(uint4*)(bp + r * 128 + ((c ^ (r & 7)) << 4)) =
                            pack8(u0, u1);
                    }
                    __syncthreads();
                } else {
                    // task 1: B already resident, only A STS
                    __syncthreads();
                    char* dp = dptr + ((t + 1) & 1) * A_STG;
#pragma unroll
                    for (int i = 0; i < 4; i++) {
                        const int r = rb + 32 * i;
                        *(uint4*)(dp + r * 128 + ((c ^ (r & 7)) << 4)) =
                            pack8(ra[i][0], ra[i][1]);
                    }
                    __syncthreads();
                }
            }
        }

        // ---- epilogue: g[b][j] = sum_a tanh(D[a,b] + bias[a]) * wh[a]
        float biasv[4][2], whv[4][2];
#pragma unroll
        for (int m = 0; m < 4; m++)
#pragma unroll
            for (int h = 0; h < 2; h++) {
                const int a = wm * 64 + m * 16 + h * 8 + gid;
                biasv[m][h] = bias_s[a];
                whv[m][h]   = wh_s[a];
            }

#pragma unroll
        for (int n = 0; n < 8; n++) {
            float p0 = 0.0f, p1 = 0.0f;
#pragma unroll
            for (int m = 0; m < 4; m++) {
                p0 += tanh_ap(acc[m][n][0] + biasv[m][0]) * whv[m][0]
                    + tanh_ap(acc[m][n][2] + biasv[m][1]) * whv[m][1];
                p1 += tanh_ap(acc[m][n][1] + biasv[m][0]) * whv[m][0]
                    + tanh_ap(acc[m][n][3] + biasv[m][1]) * whv[m][1];
            }
#pragma unroll
            for (int o = 4; o <= 16; o <<= 1) {
                p0 += __shfl_xor_sync(0xffffffffu, p0, o);
                p1 += __shfl_xor_sync(0xffffffffu, p1, o);
            }
            if (gid == 0) {
                const int col = wn * 64 + n * 8 + tid4 * 2;
                red[wm][col]     = p0;
                red[wm][col + 1] = p1;
            }
        }
        __syncthreads();
        g_buf[(size_t)tid * D + j] = red[0][tid] + red[1][tid];
        if (task + 1 < ntask) __syncthreads();
    }
}

// ---------------------------------------------------------------------------
// Kernel 2: out[b,l] = sum_j emb_iseq[b,l,j] * g[b,j]
// PDL: all emb_iseq loads (g-independent) BEFORE griddepcontrol.wait.
// (R16 config verbatim: 82.6% DRAM measured.)
// ---------------------------------------------------------------------------
__global__ void __launch_bounds__(256) k2_weight(
    const float* __restrict__ emb_iseq,  // [BSZ, MAX_LEN, D]
    float* __restrict__ out)             // [BSZ, MAX_LEN]
{
    const int b   = blockIdx.y;
    const int l0  = blockIdx.x * 64;
    const int tid = threadIdx.x;
    const int warp = tid >> 5;
    const int lane = tid & 31;
    const int l = l0 + warp * 8;

    const float4* base = (const float4*)(emb_iseq + ((size_t)b * MAX_LEN + l) * D);

    float4 e[8][2];
#pragma unroll
    for (int r = 0; r < 8; r++)
#pragma unroll
        for (int i = 0; i < 2; i++)
            e[r][i] = __ldcs(&base[r * 64 + i * 32 + lane]);

    asm volatile("griddepcontrol.wait;" ::: "memory");

    __shared__ float gs[D];
    gs[tid] = g_buf[(size_t)b * D + tid];
    __syncthreads();

    const float4* gv = (const float4*)gs;
    const float4 g0 = gv[lane];
    const float4 g1 = gv[lane + 32];

    float acc[8];
#pragma unroll
    for (int r = 0; r < 8; r++) {
        acc[r] = e[r][0].x * g0.x + e[r][0].y * g0.y + e[r][0].z * g0.z +
                 e[r][0].w * g0.w + e[r][1].x * g1.x + e[r][1].y * g1.y +
                 e[r][1].z * g1.z + e[r][1].w * g1.w;
    }
#pragma unroll
    for (int r = 0; r < 8; r++)
#pragma unroll
        for (int o = 16; o; o >>= 1)
            acc[r] += __shfl_xor_sync(0xffffffffu, acc[r], o);

    if (lane == 0) {
#pragma unroll
        for (int r = 0; r < 8; r++)
            out[(size_t)b * MAX_LEN + l + r] = acc[r];
    }
}

// ---------------------------------------------------------------------------

extern "C" void kernel_launch(void* const* d_in, const int* in_sizes, int n_in,
                              void* d_out, int out_size)
{
    const float* emb_q    = (const float*)d_in[0];
    const float* emb_iseq = (const float*)d_in[1];
    const float* w_f      = (const float*)d_in[2];
    const float* b_f      = (const float*)d_in[3];
    const float* w_h      = (const float*)d_in[4];
    float* out = (float*)d_out;

    static int pdl_ok = -1;
    if (pdl_ok < 0) {
        cudaFuncSetAttribute(k1_mma,
                             cudaFuncAttributeMaxDynamicSharedMemorySize,
                             K1_SMEM);
        pdl_ok = 1;
    }

    k1_mma<<<NCTA1, 256, K1_SMEM>>>(emb_q, w_f, b_f, w_h);

    const dim3 g2(MAX_LEN / 64, BSZ);
    if (pdl_ok == 1) {
        cudaLaunchAttribute attr[1];
        attr[0].id = cudaLaunchAttributeProgrammaticStreamSerialization;
        attr[0].val.programmaticStreamSerializationAllowed = 1;
        cudaLaunchConfig_t cfg = {};
        cfg.gridDim = g2;
        cfg.blockDim = dim3(256, 1, 1);
        cfg.dynamicSmemBytes = 0;
        cfg.stream = 0;
        cfg.attrs = attr;
        cfg.numAttrs = 1;
        if (cudaLaunchKernelEx(&cfg, k2_weight, emb_iseq, out) != cudaSuccess) {
            pdl_ok = 0;
            cudaGetLastError();
            k2_weight<<<g2, 256>>>(emb_iseq, out);
        }
    } else {
        k2_weight<<<g2, 256>>>(emb_iseq, out);
    }
}